// round 2
// baseline (speedup 1.0000x reference)
#include <cuda_runtime.h>
#include <cuda_bf16.h>
#include <cstdint>

// ============================================================================
// ConvolutionFromEdgeSetUpdate:
//   messages = relu([node[src] | node[tgt] | edge] @ W + b)   (E x 64)
//   out      = segment_sum(messages, tgt, 50000)
//
// E=800000, D=64, U=64, K=192.
//
// sm_103 (no 'a' suffix in harness toolchain) => tcgen05 unavailable.
// Engine: warp-level mma.sync.m16n8k16 bf16 (HMMA), fp32 accum, with a
// 3-product bf16 hi/lo split (Ahi*Bhi + Ahi*Blo + Alo*Bhi) for fp32-grade
// accuracy. Persistent CTAs; fused bias+relu; red.global.add.v2.f32 scatter.
// ============================================================================

#define NN_NODES 50000
#define NN_EDGES 800000
#define D_FEAT   64
#define UNITS    64
#define KDIM     192
#define TILE_M   128
#define N_TILES  (NN_EDGES / TILE_M)   // 6250
#define THREADS  256                   // 8 warps; each warp owns 16 rows
#define GRID_X   148

// SMEM: row-major bf16 tiles, row stride 200 bf16 = 400 B (16B-aligned, and
// 400 mod 128 = 16 so ldmatrix row sets are bank-conflict-free).
#define STRIDE_B   400
#define SM_A_HI    0
#define SM_A_LO    (SM_A_HI + TILE_M * STRIDE_B)     // 51200
#define SM_B_HI    (SM_A_LO + TILE_M * STRIDE_B)     // 102400
#define SM_B_LO    (SM_B_HI + UNITS * STRIDE_B)      // 128000
#define SM_TOTAL   (SM_B_LO + UNITS * STRIDE_B)      // 153600

// ---------------- helpers ----------------

__device__ __forceinline__ uint32_t smem_to_u32(const void* smem_ptr) {
    uint32_t addr;
    asm("{ .reg .u64 tmp; cvta.to.shared.u64 tmp, %1; cvt.u32.u64 %0, tmp; }"
        : "=r"(addr) : "l"(smem_ptr));
    return addr;
}

__device__ __forceinline__ void ldsm_x4(uint32_t* r, uint32_t addr) {
    asm volatile("ldmatrix.sync.aligned.m8n8.x4.shared.b16 {%0,%1,%2,%3}, [%4];"
        : "=r"(r[0]), "=r"(r[1]), "=r"(r[2]), "=r"(r[3]) : "r"(addr));
}

__device__ __forceinline__ void ldsm_x2(uint32_t* r, uint32_t addr) {
    asm volatile("ldmatrix.sync.aligned.m8n8.x2.shared.b16 {%0,%1}, [%2];"
        : "=r"(r[0]), "=r"(r[1]) : "r"(addr));
}

__device__ __forceinline__ void mma_bf16(float* c, const uint32_t* a, const uint32_t* b) {
    asm volatile(
        "mma.sync.aligned.m16n8k16.row.col.f32.bf16.bf16.f32 "
        "{%0,%1,%2,%3}, {%4,%5,%6,%7}, {%8,%9}, {%0,%1,%2,%3};"
        : "+f"(c[0]), "+f"(c[1]), "+f"(c[2]), "+f"(c[3])
        : "r"(a[0]), "r"(a[1]), "r"(a[2]), "r"(a[3]), "r"(b[0]), "r"(b[1]));
}

__device__ __forceinline__ uint32_t pack_bf16x2(float a, float b) {
    __nv_bfloat162 t = __halves2bfloat162(__float2bfloat16(a), __float2bfloat16(b));
    return *reinterpret_cast<uint32_t*>(&t);
}

// split one float into bf16 hi + bf16 lo (residual)
__device__ __forceinline__ void split2(float x, float& hi_f, float& lo_f) {
    __nv_bfloat16 h = __float2bfloat16(x);
    hi_f = __bfloat162float(h);
    lo_f = x - hi_f;
}

// ---------------- zero output (d_out is poisoned 0xAA) ----------------

__global__ void zero_out_kernel(float4* out) {
    int i = blockIdx.x * blockDim.x + threadIdx.x;
    if (i < NN_NODES * UNITS / 4) out[i] = make_float4(0.f, 0.f, 0.f, 0.f);
}

// ---------------- main fused kernel ----------------

__global__ __launch_bounds__(THREADS, 1)
void edgeconv_kernel(const float* __restrict__ node_feat,
                     const float* __restrict__ edge_feat,
                     const int*   __restrict__ src_idx,
                     const int*   __restrict__ tgt_idx,
                     const float* __restrict__ W,
                     const float* __restrict__ bias,
                     float*       __restrict__ out)
{
    extern __shared__ char smem[];
    const uint32_t smem_base = smem_to_u32(smem);
    const int tid  = threadIdx.x;
    const int wid  = tid >> 5;
    const int lane = tid & 31;

    // ---- build B = W^T hi/lo in SMEM: Bsm[n][k], n rows, k contiguous ----
    // 192 tasks: n in [0,64), seg in [0,3) covering 64 k each.
    for (int task = tid; task < 192; task += THREADS) {
        const int n = task & 63, bseg = task >> 6;
        char* rowp_hi = smem + SM_B_HI + n * STRIDE_B;
        char* rowp_lo = smem + SM_B_LO + n * STRIDE_B;
        #pragma unroll 8
        for (int j = 0; j < 64; ++j) {
            const int k = bseg * 64 + j;
            float x = W[k * UNITS + n];
            float hf, lf; split2(x, hf, lf);
            *reinterpret_cast<__nv_bfloat16*>(rowp_hi + k * 2) = __float2bfloat16(hf);
            *reinterpret_cast<__nv_bfloat16*>(rowp_lo + k * 2) = __float2bfloat16(lf);
        }
    }

    // per-thread bias for epilogue: cols j*8 + 2*(lane&3) + {0,1}
    const int t4 = lane & 3;
    const int g  = lane >> 2;
    float bj0[8], bj1[8];
    #pragma unroll
    for (int j = 0; j < 8; ++j) {
        bj0[j] = bias[j * 8 + 2 * t4];
        bj1[j] = bias[j * 8 + 2 * t4 + 1];
    }

    // ldmatrix per-lane address components (byte offsets)
    // A (16x16 frag, x4): lanes 0-15 -> rows 0-15 @ k0; 16-31 -> rows 0-15 @ k0+8
    const uint32_t a_lane_off =
        (uint32_t)((wid * 16 + (lane & 15)) * STRIDE_B + (lane >> 4) * 16);
    // B (16x8 frag, x2): lanes 0-7 -> n rows 0-7 @ k0; 8-15 -> same rows @ k0+8
    const uint32_t b_lane_off =
        (uint32_t)((lane & 7) * STRIDE_B + ((lane >> 3) & 1) * 16);

    const uint32_t aHI = smem_base + SM_A_HI + a_lane_off;
    const uint32_t aLO = smem_base + SM_A_LO + a_lane_off;
    const uint32_t bHI = smem_base + SM_B_HI + b_lane_off;
    const uint32_t bLO = smem_base + SM_B_LO + b_lane_off;

    __syncthreads();   // B tiles ready

    for (int tile = blockIdx.x; tile < N_TILES; tile += GRID_X) {
        // ================= gather + convert A tile (hi/lo) =================
        // 384 tasks: row in [0,128), seg in {src, tgt, edge}; 16B stores.
        for (int task = tid; task < 3 * TILE_M; task += THREADS) {
            const int row = task & (TILE_M - 1);
            const int seg = task >> 7;              // 0,1,2
            const int e   = tile * TILE_M + row;
            const float* p;
            if (seg == 0)      p = node_feat + (size_t)__ldg(src_idx + e) * D_FEAT;
            else if (seg == 1) p = node_feat + (size_t)__ldg(tgt_idx + e) * D_FEAT;
            else               p = edge_feat + (size_t)e * D_FEAT;
            const float4* p4 = reinterpret_cast<const float4*>(p);
            char* dst_hi = smem + SM_A_HI + row * STRIDE_B + seg * 128;
            char* dst_lo = smem + SM_A_LO + row * STRIDE_B + seg * 128;
            #pragma unroll
            for (int q = 0; q < 8; ++q) {          // 8 x (8 floats -> 16B hi + 16B lo)
                float4 v0 = __ldg(p4 + 2 * q);
                float4 v1 = __ldg(p4 + 2 * q + 1);
                float h, l;
                uint4 hh, ll;
                float h0,l0,h1,l1,h2,l2,h3,l3;
                split2(v0.x, h0, l0); split2(v0.y, h1, l1);
                split2(v0.z, h2, l2); split2(v0.w, h3, l3);
                hh.x = pack_bf16x2(h0, h1); hh.y = pack_bf16x2(h2, h3);
                ll.x = pack_bf16x2(l0, l1); ll.y = pack_bf16x2(l2, l3);
                split2(v1.x, h0, l0); split2(v1.y, h1, l1);
                split2(v1.z, h2, l2); split2(v1.w, h3, l3);
                hh.z = pack_bf16x2(h0, h1); hh.w = pack_bf16x2(h2, h3);
                ll.z = pack_bf16x2(l0, l1); ll.w = pack_bf16x2(l2, l3);
                *reinterpret_cast<uint4*>(dst_hi + q * 16) = hh;
                *reinterpret_cast<uint4*>(dst_lo + q * 16) = ll;
                (void)h; (void)l;
            }
        }
        __syncthreads();

        // ================= MMA: 16 rows per warp, full N=64, K=192 ==========
        float acc[8][4];
        #pragma unroll
        for (int j = 0; j < 8; ++j) {
            acc[j][0] = 0.f; acc[j][1] = 0.f; acc[j][2] = 0.f; acc[j][3] = 0.f;
        }

        #pragma unroll
        for (int ks = 0; ks < KDIM / 16; ++ks) {   // 12 k-steps
            const uint32_t kb = (uint32_t)(ks * 32); // k0*2 bytes
            uint32_t ahi[4], alo[4];
            ldsm_x4(ahi, aHI + kb);
            ldsm_x4(alo, aLO + kb);
            #pragma unroll
            for (int j = 0; j < 8; ++j) {
                uint32_t bhi[2], blo[2];
                const uint32_t bj = (uint32_t)(j * 8 * STRIDE_B) + kb;
                ldsm_x2(bhi, bHI + bj);
                ldsm_x2(blo, bLO + bj);
                mma_bf16(acc[j], ahi, bhi);
                mma_bf16(acc[j], ahi, blo);
                mma_bf16(acc[j], alo, bhi);
            }
        }
        __syncthreads();   // A tile free for next iteration's gather

        // ================= epilogue: bias + relu + scatter ==================
        // thread holds rows {g, g+8} of warp's 16-row block, cols j*8+2t4+{0,1}
        {
            const int e0 = tile * TILE_M + wid * 16 + g;
            const int e1 = e0 + 8;
            const int tgt0 = __ldg(tgt_idx + e0);
            const int tgt1 = __ldg(tgt_idx + e1);
            float* o0 = out + (size_t)tgt0 * UNITS + 2 * t4;
            float* o1 = out + (size_t)tgt1 * UNITS + 2 * t4;
            #pragma unroll
            for (int j = 0; j < 8; ++j) {
                float v0 = fmaxf(acc[j][0] + bj0[j], 0.f);
                float v1 = fmaxf(acc[j][1] + bj1[j], 0.f);
                float v2 = fmaxf(acc[j][2] + bj0[j], 0.f);
                float v3 = fmaxf(acc[j][3] + bj1[j], 0.f);
                asm volatile("red.global.add.v2.f32 [%0], {%1, %2};"
                             :: "l"(o0 + j * 8), "f"(v0), "f"(v1) : "memory");
                asm volatile("red.global.add.v2.f32 [%0], {%1, %2};"
                             :: "l"(o1 + j * 8), "f"(v2), "f"(v3) : "memory");
            }
        }
    }
}

// ---------------- launch ----------------

extern "C" void kernel_launch(void* const* d_in, const int* in_sizes, int n_in,
                              void* d_out, int out_size) {
    const float* node_feat = (const float*)d_in[0];
    const float* edge_feat = (const float*)d_in[1];
    const int*   src_idx   = (const int*)d_in[2];
    const int*   tgt_idx   = (const int*)d_in[3];
    const float* W         = (const float*)d_in[4];
    const float* b         = (const float*)d_in[5];
    float* out = (float*)d_out;

    int n4 = NN_NODES * UNITS / 4;
    zero_out_kernel<<<(n4 + 255) / 256, 256>>>((float4*)out);

    static int configured = 0;
    if (!configured) {
        cudaFuncSetAttribute(edgeconv_kernel,
                             cudaFuncAttributeMaxDynamicSharedMemorySize, SM_TOTAL);
        configured = 1;
    }
    edgeconv_kernel<<<GRID_X, THREADS, SM_TOTAL>>>(
        node_feat, edge_feat, src_idx, tgt_idx, W, b, out);
}